// round 1
// baseline (speedup 1.0000x reference)
#include <cuda_runtime.h>
#include <math.h>

#define OBS_DIM 256
#define ACT_DIM 64
#define T_TOT   22
#define HID     32
#define MAXW    15
#define NSTEP   15      // CENTER+1 timesteps fed to GRU
#define NGATE   96
#define KDIM    320     // OBS_DIM + ACT_DIM
#define MAXB    8192

// GRU pre-activation scratch: GI[(b*15+t)*96 + g]
__device__ float g_GI[(size_t)MAXB * NSTEP * NGATE];

// ---------- packed f32x2 helpers (Blackwell sm_103a) ----------
__device__ __forceinline__ unsigned long long pk2(float lo, float hi) {
    unsigned long long r;
    asm("mov.b64 %0, {%1, %2};" : "=l"(r) : "f"(lo), "f"(hi));
    return r;
}
__device__ __forceinline__ void upk2(unsigned long long v, float& lo, float& hi) {
    asm("mov.b64 {%0, %1}, %2;" : "=f"(lo), "=f"(hi) : "l"(v));
}
__device__ __forceinline__ unsigned long long ffma2(unsigned long long a,
                                                    unsigned long long b,
                                                    unsigned long long c) {
    unsigned long long d;
    asm("fma.rn.f32x2 %0, %1, %2, %3;" : "=l"(d) : "l"(a), "l"(b), "l"(c));
    return d;
}

// ---------- warp reduce helpers ----------
__device__ __forceinline__ float wsum(float x) {
#pragma unroll
    for (int o = 16; o; o >>= 1) x += __shfl_xor_sync(0xffffffffu, x, o);
    return x;
}
__device__ __forceinline__ float wmax(float x) {
#pragma unroll
    for (int o = 16; o; o >>= 1) x = fmaxf(x, __shfl_xor_sync(0xffffffffu, x, o));
    return x;
}

__device__ __forceinline__ float sigm(float x) { return 1.f / (1.f + __expf(-x)); }
__device__ __forceinline__ float tanh_fast(float x) {
    float e = __expf(-2.f * fabsf(x));
    float r = (1.f - e) / (1.f + e);
    return copysignf(r, x);
}

// =====================================================================
// Kernel 1: GI = X @ W_ih^T + b_ih   (M=B*15, N=96, K=320), fp32 via f32x2
// Block 256 threads: tx = tid&7 (12 cols each), ty = tid>>3 (4 rows each)
// =====================================================================
#define BM 128
#define BK 32

__global__ __launch_bounds__(256) void k_gemm(
    const float* __restrict__ obs, const float* __restrict__ act,
    const float* __restrict__ Wih, const float* __restrict__ bih, int Bn)
{
    __shared__ __align__(16) float Xs[BM][33];   // [m][k], stride 33 -> conflict-free scalar reads
    __shared__ __align__(16) float Ws[BK][100];  // [k][n], stride 100 -> aligned float2 reads

    const int Mtot = Bn * NSTEP;
    const int tid = threadIdx.x;
    const int tx = tid & 7, ty = tid >> 3;
    const int m_base = blockIdx.x * BM;
    const int lm  = tid >> 3;   // 0..31
    const int lk4 = tid & 7;    // float4 column within k-tile

    unsigned long long acc[4][6];
#pragma unroll
    for (int i = 0; i < 4; i++)
#pragma unroll
        for (int p = 0; p < 6; p++) acc[i][p] = 0ULL;

    for (int kt = 0; kt < KDIM; kt += BK) {
        // --- load X tile (128 x 32) ---
#pragma unroll
        for (int pass = 0; pass < 4; pass++) {
            int m  = lm + 32 * pass;
            int gm = m_base + m;
            int gmc = gm < Mtot ? gm : Mtot - 1;
            int bb = gmc / NSTEP;
            int tt = gmc - bb * NSTEP;
            int k0 = kt + 4 * lk4;
            float4 v;
            if (kt < OBS_DIM)
                v = *(const float4*)(obs + ((size_t)(bb * T_TOT + tt)) * OBS_DIM + k0);
            else
                v = *(const float4*)(act + ((size_t)(bb * T_TOT + tt)) * ACT_DIM + (k0 - OBS_DIM));
            Xs[m][4 * lk4 + 0] = v.x;
            Xs[m][4 * lk4 + 1] = v.y;
            Xs[m][4 * lk4 + 2] = v.z;
            Xs[m][4 * lk4 + 3] = v.w;
        }
        // --- load W tile (32k x 96n), transposed to [k][n] ---
#pragma unroll
        for (int pass = 0; pass < 3; pass++) {
            int n = lm + 32 * pass;
            float4 v = *(const float4*)(Wih + (size_t)n * KDIM + kt + 4 * lk4);
            Ws[4 * lk4 + 0][n] = v.x;
            Ws[4 * lk4 + 1][n] = v.y;
            Ws[4 * lk4 + 2][n] = v.z;
            Ws[4 * lk4 + 3][n] = v.w;
        }
        __syncthreads();

        const int n0 = tx * 12, m0 = ty * 4;
#pragma unroll
        for (int k = 0; k < BK; k++) {
            unsigned long long w[6];
#pragma unroll
            for (int p = 0; p < 6; p++) {
                float2 wv = *(const float2*)&Ws[k][n0 + 2 * p];
                w[p] = pk2(wv.x, wv.y);
            }
#pragma unroll
            for (int i = 0; i < 4; i++) {
                float x = Xs[m0 + i][k];
                unsigned long long xx = pk2(x, x);
#pragma unroll
                for (int p = 0; p < 6; p++) acc[i][p] = ffma2(xx, w[p], acc[i][p]);
            }
        }
        __syncthreads();
    }

    const int n0 = tx * 12, m0 = ty * 4;
#pragma unroll
    for (int i = 0; i < 4; i++) {
        int gm = m_base + m0 + i;
        if (gm >= Mtot) continue;
#pragma unroll
        for (int p = 0; p < 6; p++) {
            float lo, hi;
            upk2(acc[i][p], lo, hi);
            int n = n0 + 2 * p;
            float2 o;
            o.x = lo + bih[n];
            o.y = hi + bih[n + 1];
            *(float2*)(g_GI + (size_t)gm * NGATE + n) = o;
        }
    }
}

// =====================================================================
// Kernel 2: per-warp GRU recurrence + features + LN + MLP + argmax
//           writes window_len and mask portions of out.
// =====================================================================
__global__ __launch_bounds__(256) void k_gru(
    const float* __restrict__ obs, const float* __restrict__ act,
    const float* __restrict__ Whh, const float* __restrict__ bhh,
    const float* __restrict__ lng, const float* __restrict__ lnb,
    const float* __restrict__ W1, const float* __restrict__ b1,
    const float* __restrict__ W2, const float* __restrict__ b2,
    const float* __restrict__ W3, const float* __restrict__ b3,
    float* __restrict__ out, int Bn)
{
    __shared__ float w1s[64 * 35];
    __shared__ float w2s[32 * 65];   // padded stride 65 (conflict-free)
    __shared__ float w3s[14 * 33];   // padded stride 33
    __shared__ float b1s[64], b2s[32], b3s[14];
    __shared__ float gms[35], bts[35];
    __shared__ float wbuf[8][144];   // per-warp scratch: feats[0:35], x1[40:104], x2[104:136]

    const int tid = threadIdx.x;
    for (int i = tid; i < 64 * 35; i += 256) w1s[i] = W1[i];
    for (int i = tid; i < 32 * 64; i += 256) w2s[(i >> 6) * 65 + (i & 63)] = W2[i];
    for (int i = tid; i < 14 * 32; i += 256) w3s[(i >> 5) * 33 + (i & 31)] = W3[i];
    if (tid < 64) b1s[tid] = b1[tid];
    if (tid < 32) b2s[tid] = b2[tid];
    if (tid < 14) b3s[tid] = b3[tid];
    if (tid < 35) { gms[tid] = lng[tid]; bts[tid] = lnb[tid]; }
    __syncthreads();

    const int warp = tid >> 5, j = tid & 31;
    const int b = blockIdx.x * 8 + warp;
    if (b >= Bn) return;

    // ---- GRU: W_hh rows (j, 32+j, 64+j) in registers ----
    float wr[HID], wz[HID], wn[HID];
#pragma unroll
    for (int q = 0; q < 8; q++) {
        float4 v = ((const float4*)(Whh + (size_t)j * HID))[q];
        wr[4 * q] = v.x; wr[4 * q + 1] = v.y; wr[4 * q + 2] = v.z; wr[4 * q + 3] = v.w;
    }
#pragma unroll
    for (int q = 0; q < 8; q++) {
        float4 v = ((const float4*)(Whh + (size_t)(32 + j) * HID))[q];
        wz[4 * q] = v.x; wz[4 * q + 1] = v.y; wz[4 * q + 2] = v.z; wz[4 * q + 3] = v.w;
    }
#pragma unroll
    for (int q = 0; q < 8; q++) {
        float4 v = ((const float4*)(Whh + (size_t)(64 + j) * HID))[q];
        wn[4 * q] = v.x; wn[4 * q + 1] = v.y; wn[4 * q + 2] = v.z; wn[4 * q + 3] = v.w;
    }
    const float bhr = bhh[j], bhz = bhh[32 + j], bhn = bhh[64 + j];

    const float* gip = g_GI + (size_t)b * NSTEP * NGATE;
    float gr = gip[j], gz = gip[32 + j], gn = gip[64 + j];
    float h = 0.f;

#pragma unroll 1
    for (int t = 0; t < NSTEP; t++) {
        float ngr = 0.f, ngz = 0.f, ngn = 0.f;
        if (t + 1 < NSTEP) {
            const float* q = gip + (size_t)(t + 1) * NGATE;
            ngr = q[j]; ngz = q[32 + j]; ngn = q[64 + j];
        }
        float ar = bhr, az = bhz, an = bhn;
#pragma unroll
        for (int k = 0; k < HID; k++) {
            float hk = __shfl_sync(0xffffffffu, h, k);
            ar = fmaf(wr[k], hk, ar);
            az = fmaf(wz[k], hk, az);
            an = fmaf(wn[k], hk, an);
        }
        float r = sigm(gr + ar);
        float z = sigm(gz + az);
        float n = tanh_fast(gn + r * an);
        h = (1.f - z) * n + z * h;
        gr = ngr; gz = ngz; gn = ngn;
    }

    // ---- features ----
    const float* op = obs + (size_t)b * T_TOT * OBS_DIM;
    float o11[8], o12[8], o13[8], o14[8];
#pragma unroll
    for (int i = 0; i < 8; i++) {
        o11[i] = op[11 * OBS_DIM + i * 32 + j];
        o12[i] = op[12 * OBS_DIM + i * 32 + j];
        o13[i] = op[13 * OBS_DIM + i * 32 + j];
        o14[i] = op[14 * OBS_DIM + i * 32 + j];
    }

    // entropy of softmax(obs_t)
    float mx = o14[0];
#pragma unroll
    for (int i = 1; i < 8; i++) mx = fmaxf(mx, o14[i]);
    mx = wmax(mx);
    float s = 0.f;
#pragma unroll
    for (int i = 0; i < 8; i++) s += __expf(o14[i] - mx);
    s = wsum(s);
    float inv_s = 1.f / s;
    float es = 0.f;
#pragma unroll
    for (int i = 0; i < 8; i++) {
        float p = __expf(o14[i] - mx) * inv_s;
        es += p * __logf(p + 1e-8f);
    }
    es = wsum(es);
    float entropy = -es;

    // rate of change
    float d2a = 0.f, d2b = 0.f, d2c = 0.f;
#pragma unroll
    for (int i = 0; i < 8; i++) {
        float da = o12[i] - o11[i]; d2a = fmaf(da, da, d2a);
        float db = o13[i] - o12[i]; d2b = fmaf(db, db, d2b);
        float dc = o14[i] - o13[i]; d2c = fmaf(dc, dc, d2c);
    }
    d2a = wsum(d2a); d2b = wsum(d2b); d2c = wsum(d2c);
    float roc = (sqrtf(d2a) + sqrtf(d2b) + sqrtf(d2c)) * (1.f / 3.f);

    // correlation
    float osum = 0.f;
#pragma unroll
    for (int i = 0; i < 8; i++) osum += o14[i];
    osum = wsum(osum);
    float om = osum * (1.f / 256.f);
    const float* ap = act + ((size_t)b * T_TOT + 13) * ACT_DIM;
    float a0 = ap[j], a1 = ap[32 + j];
    float am = wsum(a0 + a1) * (1.f / 256.f);
    float num = 0.f, do2 = 0.f;
#pragma unroll
    for (int i = 0; i < 8; i++) {
        float oc = o14[i] - om;
        do2 = fmaf(oc, oc, do2);
        float acv = ((i == 0) ? a0 : (i == 1) ? a1 : 0.f) - am;
        num = fmaf(oc, acv, num);
    }
    float da2 = (a0 - am) * (a0 - am) + (a1 - am) * (a1 - am) + 6.f * am * am;
    num = wsum(num); do2 = wsum(do2); da2 = wsum(da2);
    float corr = num / (sqrtf(do2) * sqrtf(da2) + 1e-8f);

    // ---- layernorm + MLP ----
    float* fb = wbuf[warp];
    if (j == 0) { fb[0] = entropy; fb[1] = roc; fb[2] = corr; }
    fb[3 + j] = h;
    __syncwarp();

    float v1 = fb[j];
    float v2 = (j < 3) ? fb[32 + j] : 0.f;
    float mu = wsum(v1 + v2) * (1.f / 35.f);
    float dd1 = v1 - mu;
    float dd2 = (j < 3) ? (v2 - mu) : 0.f;
    float var = wsum(dd1 * dd1 + dd2 * dd2) * (1.f / 35.f);
    float scl = rsqrtf(var + 1e-5f);
    __syncwarp();
    fb[j] = dd1 * scl * gms[j] + bts[j];
    if (j < 3) fb[32 + j] = dd2 * scl * gms[32 + j] + bts[32 + j];
    __syncwarp();

    float* fx1 = fb + 40;
    {
        float acc0 = b1s[j], acc1 = b1s[32 + j];
#pragma unroll
        for (int k = 0; k < 35; k++) {
            float f = fb[k];
            acc0 = fmaf(w1s[j * 35 + k], f, acc0);
            acc1 = fmaf(w1s[(32 + j) * 35 + k], f, acc1);
        }
        fx1[j] = fmaxf(acc0, 0.f);
        fx1[32 + j] = fmaxf(acc1, 0.f);
    }
    __syncwarp();

    float* fx2 = fb + 104;
    {
        float acc = b2s[j];
#pragma unroll
        for (int k = 0; k < 64; k++) acc = fmaf(w2s[j * 65 + k], fx1[k], acc);
        fx2[j] = fmaxf(acc, 0.f);
    }
    __syncwarp();

    float val = -INFINITY;
    if (j < 14) {
        float acc = b3s[j];
#pragma unroll
        for (int k = 0; k < 32; k++) acc = fmaf(w3s[j * 33 + k], fx2[k], acc);
        val = acc;
    }
    int idx = j;
#pragma unroll
    for (int off = 16; off; off >>= 1) {
        float ov = __shfl_down_sync(0xffffffffu, val, off);
        int oi = __shfl_down_sync(0xffffffffu, idx, off);
        if (ov > val || (ov == val && oi < idx)) { val = ov; idx = oi; }
    }
    idx = __shfl_sync(0xffffffffu, idx, 0);

    int wl = idx + 2;
    int s_off = (wl - 1) >> 1;
    int e_off = wl >> 1;

    if (j == 0) out[b] = (float)wl;
    if (j < MAXW) {
        int offp = j - 7;
        float mval = (offp >= -s_off && offp <= e_off) ? 1.f : 0.f;
        out[(size_t)Bn + (size_t)Bn * MAXW * KDIM + (size_t)b * MAXW + j] = mval;
    }
}

// =====================================================================
// Kernel 3: padded window writer. One warp per (b, o) row.
// =====================================================================
__global__ __launch_bounds__(256) void k_win(
    const float* __restrict__ obs, const float* __restrict__ act,
    const float* __restrict__ maskbuf, float* __restrict__ pw, int Bn)
{
    int wg = (blockIdx.x * blockDim.x + threadIdx.x) >> 5;
    int j = threadIdx.x & 31;
    if (wg >= Bn * MAXW) return;
    int b = wg / MAXW;
    int o = wg - b * MAXW;

    float m = maskbuf[(size_t)b * MAXW + o];
    float4* dst = (float4*)(pw + (size_t)(b * MAXW + o) * KDIM);

    if (m != 0.f) {
        const float4* so = (const float4*)(obs + (size_t)(b * T_TOT + 7 + o) * OBS_DIM);
        const float4* sa = (const float4*)(act + (size_t)(b * T_TOT + 7 + o) * ACT_DIM);
        dst[j] = so[j];
        dst[32 + j] = so[32 + j];
        if (j < 16) dst[64 + j] = sa[j];
    } else {
        float4 z = make_float4(0.f, 0.f, 0.f, 0.f);
        dst[j] = z;
        dst[32 + j] = z;
        if (j < 16) dst[64 + j] = z;
    }
}

// =====================================================================
extern "C" void kernel_launch(void* const* d_in, const int* in_sizes, int n_in,
                              void* d_out, int out_size)
{
    const float* obs = (const float*)d_in[0];
    const float* act = (const float*)d_in[1];
    const float* Wih = (const float*)d_in[2];
    const float* Whh = (const float*)d_in[3];
    const float* bih = (const float*)d_in[4];
    const float* bhh = (const float*)d_in[5];
    const float* lng = (const float*)d_in[6];
    const float* lnb = (const float*)d_in[7];
    const float* W1  = (const float*)d_in[8];
    const float* b1  = (const float*)d_in[9];
    const float* W2  = (const float*)d_in[10];
    const float* b2  = (const float*)d_in[11];
    const float* W3  = (const float*)d_in[12];
    const float* b3  = (const float*)d_in[13];

    int Bn = in_sizes[0] / (T_TOT * OBS_DIM);
    if (Bn > MAXB) Bn = MAXB;
    float* out = (float*)d_out;

    int Mtot = Bn * NSTEP;
    int gemm_blocks = (Mtot + BM - 1) / BM;
    k_gemm<<<gemm_blocks, 256>>>(obs, act, Wih, bih, Bn);

    int gru_blocks = (Bn + 7) / 8;
    k_gru<<<gru_blocks, 256>>>(obs, act, Whh, bhh, lng, lnb,
                               W1, b1, W2, b2, W3, b3, out, Bn);

    float* pw = out + Bn;                                  // padded_window region
    const float* maskbuf = out + (size_t)Bn + (size_t)Bn * MAXW * KDIM;
    int win_threads = Bn * MAXW * 32;
    k_win<<<(win_threads + 255) / 256, 256>>>(obs, act, maskbuf, pw, Bn);
}

// round 2
// speedup vs baseline: 1.0904x; 1.0904x over previous
#include <cuda_runtime.h>
#include <math.h>

#define OBS_DIM 256
#define ACT_DIM 64
#define T_TOT   22
#define HID     32
#define MAXW    15
#define NSTEP   15      // CENTER+1 timesteps fed to GRU
#define NGATE   96
#define KDIM    320     // OBS_DIM + ACT_DIM
#define MAXB    8192

// GRU pre-activation scratch: GI[(b*15+t)*96 + g]
__device__ float g_GI[(size_t)MAXB * NSTEP * NGATE];

// ---------- packed f32x2 helpers (Blackwell sm_103a) ----------
__device__ __forceinline__ unsigned long long pk2(float lo, float hi) {
    unsigned long long r;
    asm("mov.b64 %0, {%1, %2};" : "=l"(r) : "f"(lo), "f"(hi));
    return r;
}
__device__ __forceinline__ void upk2(unsigned long long v, float& lo, float& hi) {
    asm("mov.b64 {%0, %1}, %2;" : "=f"(lo), "=f"(hi) : "l"(v));
}
__device__ __forceinline__ unsigned long long ffma2(unsigned long long a,
                                                    unsigned long long b,
                                                    unsigned long long c) {
    unsigned long long d;
    asm("fma.rn.f32x2 %0, %1, %2, %3;" : "=l"(d) : "l"(a), "l"(b), "l"(c));
    return d;
}

// ---------- warp reduce helpers ----------
__device__ __forceinline__ float wsum(float x) {
#pragma unroll
    for (int o = 16; o; o >>= 1) x += __shfl_xor_sync(0xffffffffu, x, o);
    return x;
}
__device__ __forceinline__ float wmax(float x) {
#pragma unroll
    for (int o = 16; o; o >>= 1) x = fmaxf(x, __shfl_xor_sync(0xffffffffu, x, o));
    return x;
}

__device__ __forceinline__ float sigm(float x) { return 1.f / (1.f + __expf(-x)); }
__device__ __forceinline__ float tanh_fast(float x) {
    float e = __expf(-2.f * fabsf(x));
    float r = (1.f - e) / (1.f + e);
    return copysignf(r, x);
}

// =====================================================================
// Kernel 1: GI = X @ W_ih^T + b_ih   (M=B*15, N=96, K=320), fp32 via f32x2
// 128 threads: tx = tid&7 -> 12 n each, ty = tid>>3 -> 8 m each (8x12 tile)
// =====================================================================
#define BM 128
#define BK 32

__global__ __launch_bounds__(128, 3) void k_gemm(
    const float* __restrict__ obs, const float* __restrict__ act,
    const float* __restrict__ Wih, const float* __restrict__ bih, int Bn)
{
    __shared__ __align__(16) float Xs[BM][33];   // [m][k], scalar broadcast reads
    __shared__ __align__(16) float Ws[BK][100];  // [k][n], 100*4B = 25*16B aligned rows

    const int Mtot = Bn * NSTEP;
    const int tid = threadIdx.x;
    const int tx = tid & 7, ty = tid >> 3;       // ty 0..15
    const int m_base = blockIdx.x * BM;
    const int lm  = tid >> 3;                    // 0..15
    const int lk4 = tid & 7;                     // float4 column within k-tile

    const int n0 = tx * 12, m0 = ty * 8;

    unsigned long long acc[8][6];
#pragma unroll
    for (int i = 0; i < 8; i++)
#pragma unroll
        for (int p = 0; p < 6; p++) acc[i][p] = 0ULL;

    for (int kt = 0; kt < KDIM; kt += BK) {
        // --- load X tile (128 x 32): 8 passes of 16 rows ---
#pragma unroll
        for (int pass = 0; pass < 8; pass++) {
            int m  = lm + 16 * pass;
            int gm = m_base + m;
            int gmc = gm < Mtot ? gm : Mtot - 1;
            int bb = gmc / NSTEP;
            int tt = gmc - bb * NSTEP;
            int k0 = kt + 4 * lk4;
            float4 v;
            if (kt < OBS_DIM)
                v = *(const float4*)(obs + ((size_t)(bb * T_TOT + tt)) * OBS_DIM + k0);
            else
                v = *(const float4*)(act + ((size_t)(bb * T_TOT + tt)) * ACT_DIM + (k0 - OBS_DIM));
            Xs[m][4 * lk4 + 0] = v.x;
            Xs[m][4 * lk4 + 1] = v.y;
            Xs[m][4 * lk4 + 2] = v.z;
            Xs[m][4 * lk4 + 3] = v.w;
        }
        // --- load W tile (32k x 96n), transposed to [k][n]: 6 passes of 16 rows ---
#pragma unroll
        for (int pass = 0; pass < 6; pass++) {
            int n = lm + 16 * pass;
            float4 v = *(const float4*)(Wih + (size_t)n * KDIM + kt + 4 * lk4);
            Ws[4 * lk4 + 0][n] = v.x;
            Ws[4 * lk4 + 1][n] = v.y;
            Ws[4 * lk4 + 2][n] = v.z;
            Ws[4 * lk4 + 3][n] = v.w;
        }
        __syncthreads();

#pragma unroll 8
        for (int k = 0; k < BK; k++) {
            // 12 weights via 3x LDS.128 (n0 = tx*12 -> 48B-aligned)
            float4 wa = *(const float4*)&Ws[k][n0];
            float4 wb = *(const float4*)&Ws[k][n0 + 4];
            float4 wc = *(const float4*)&Ws[k][n0 + 8];
            unsigned long long w0 = pk2(wa.x, wa.y);
            unsigned long long w1 = pk2(wa.z, wa.w);
            unsigned long long w2 = pk2(wb.x, wb.y);
            unsigned long long w3 = pk2(wb.z, wb.w);
            unsigned long long w4 = pk2(wc.x, wc.y);
            unsigned long long w5 = pk2(wc.z, wc.w);
#pragma unroll
            for (int i = 0; i < 8; i++) {
                float x = Xs[m0 + i][k];
                unsigned long long xx = pk2(x, x);
                acc[i][0] = ffma2(xx, w0, acc[i][0]);
                acc[i][1] = ffma2(xx, w1, acc[i][1]);
                acc[i][2] = ffma2(xx, w2, acc[i][2]);
                acc[i][3] = ffma2(xx, w3, acc[i][3]);
                acc[i][4] = ffma2(xx, w4, acc[i][4]);
                acc[i][5] = ffma2(xx, w5, acc[i][5]);
            }
        }
        __syncthreads();
    }

    // bias for this thread's 12 columns
    float4 bv0 = *(const float4*)(bih + n0);
    float4 bv1 = *(const float4*)(bih + n0 + 4);
    float4 bv2 = *(const float4*)(bih + n0 + 8);

#pragma unroll
    for (int i = 0; i < 8; i++) {
        int gm = m_base + m0 + i;
        if (gm >= Mtot) continue;
        float f[12];
#pragma unroll
        for (int p = 0; p < 6; p++) upk2(acc[i][p], f[2 * p], f[2 * p + 1]);
        float4 o0 = make_float4(f[0] + bv0.x, f[1] + bv0.y, f[2] + bv0.z, f[3] + bv0.w);
        float4 o1 = make_float4(f[4] + bv1.x, f[5] + bv1.y, f[6] + bv1.z, f[7] + bv1.w);
        float4 o2 = make_float4(f[8] + bv2.x, f[9] + bv2.y, f[10] + bv2.z, f[11] + bv2.w);
        float* dst = g_GI + (size_t)gm * NGATE + n0;
        *(float4*)(dst + 0) = o0;
        *(float4*)(dst + 4) = o1;
        *(float4*)(dst + 8) = o2;
    }
}

// =====================================================================
// Kernel 2: per-warp GRU recurrence + features + LN + MLP + argmax
//           writes window_len and mask portions of out.
// =====================================================================
__global__ __launch_bounds__(256) void k_gru(
    const float* __restrict__ obs, const float* __restrict__ act,
    const float* __restrict__ Whh, const float* __restrict__ bhh,
    const float* __restrict__ lng, const float* __restrict__ lnb,
    const float* __restrict__ W1, const float* __restrict__ b1,
    const float* __restrict__ W2, const float* __restrict__ b2,
    const float* __restrict__ W3, const float* __restrict__ b3,
    float* __restrict__ out, int Bn)
{
    __shared__ float w1s[64 * 35];
    __shared__ float w2s[32 * 65];   // padded stride 65 (conflict-free)
    __shared__ float w3s[14 * 33];   // padded stride 33
    __shared__ float b1s[64], b2s[32], b3s[14];
    __shared__ float gms[35], bts[35];
    __shared__ float wbuf[8][144];   // per-warp scratch: feats[0:35], x1[40:104], x2[104:136]

    const int tid = threadIdx.x;
    for (int i = tid; i < 64 * 35; i += 256) w1s[i] = W1[i];
    for (int i = tid; i < 32 * 64; i += 256) w2s[(i >> 6) * 65 + (i & 63)] = W2[i];
    for (int i = tid; i < 14 * 32; i += 256) w3s[(i >> 5) * 33 + (i & 31)] = W3[i];
    if (tid < 64) b1s[tid] = b1[tid];
    if (tid < 32) b2s[tid] = b2[tid];
    if (tid < 14) b3s[tid] = b3[tid];
    if (tid < 35) { gms[tid] = lng[tid]; bts[tid] = lnb[tid]; }
    __syncthreads();

    const int warp = tid >> 5, j = tid & 31;
    const int b = blockIdx.x * 8 + warp;
    if (b >= Bn) return;

    // ---- GRU: W_hh rows (j, 32+j, 64+j) in registers ----
    float wr[HID], wz[HID], wn[HID];
#pragma unroll
    for (int q = 0; q < 8; q++) {
        float4 v = ((const float4*)(Whh + (size_t)j * HID))[q];
        wr[4 * q] = v.x; wr[4 * q + 1] = v.y; wr[4 * q + 2] = v.z; wr[4 * q + 3] = v.w;
    }
#pragma unroll
    for (int q = 0; q < 8; q++) {
        float4 v = ((const float4*)(Whh + (size_t)(32 + j) * HID))[q];
        wz[4 * q] = v.x; wz[4 * q + 1] = v.y; wz[4 * q + 2] = v.z; wz[4 * q + 3] = v.w;
    }
#pragma unroll
    for (int q = 0; q < 8; q++) {
        float4 v = ((const float4*)(Whh + (size_t)(64 + j) * HID))[q];
        wn[4 * q] = v.x; wn[4 * q + 1] = v.y; wn[4 * q + 2] = v.z; wn[4 * q + 3] = v.w;
    }
    const float bhr = bhh[j], bhz = bhh[32 + j], bhn = bhh[64 + j];

    const float* gip = g_GI + (size_t)b * NSTEP * NGATE;
    float gr = gip[j], gz = gip[32 + j], gn = gip[64 + j];
    float h = 0.f;

#pragma unroll 1
    for (int t = 0; t < NSTEP; t++) {
        float ngr = 0.f, ngz = 0.f, ngn = 0.f;
        if (t + 1 < NSTEP) {
            const float* q = gip + (size_t)(t + 1) * NGATE;
            ngr = q[j]; ngz = q[32 + j]; ngn = q[64 + j];
        }
        float ar = bhr, az = bhz, an = bhn;
#pragma unroll
        for (int k = 0; k < HID; k++) {
            float hk = __shfl_sync(0xffffffffu, h, k);
            ar = fmaf(wr[k], hk, ar);
            az = fmaf(wz[k], hk, az);
            an = fmaf(wn[k], hk, an);
        }
        float r = sigm(gr + ar);
        float z = sigm(gz + az);
        float n = tanh_fast(gn + r * an);
        h = (1.f - z) * n + z * h;
        gr = ngr; gz = ngz; gn = ngn;
    }

    // ---- features ----
    const float* op = obs + (size_t)b * T_TOT * OBS_DIM;
    float o11[8], o12[8], o13[8], o14[8];
#pragma unroll
    for (int i = 0; i < 8; i++) {
        o11[i] = op[11 * OBS_DIM + i * 32 + j];
        o12[i] = op[12 * OBS_DIM + i * 32 + j];
        o13[i] = op[13 * OBS_DIM + i * 32 + j];
        o14[i] = op[14 * OBS_DIM + i * 32 + j];
    }

    // entropy of softmax(obs_t)
    float mx = o14[0];
#pragma unroll
    for (int i = 1; i < 8; i++) mx = fmaxf(mx, o14[i]);
    mx = wmax(mx);
    float s = 0.f;
#pragma unroll
    for (int i = 0; i < 8; i++) s += __expf(o14[i] - mx);
    s = wsum(s);
    float inv_s = 1.f / s;
    float es = 0.f;
#pragma unroll
    for (int i = 0; i < 8; i++) {
        float p = __expf(o14[i] - mx) * inv_s;
        es += p * __logf(p + 1e-8f);
    }
    es = wsum(es);
    float entropy = -es;

    // rate of change
    float d2a = 0.f, d2b = 0.f, d2c = 0.f;
#pragma unroll
    for (int i = 0; i < 8; i++) {
        float da = o12[i] - o11[i]; d2a = fmaf(da, da, d2a);
        float db = o13[i] - o12[i]; d2b = fmaf(db, db, d2b);
        float dc = o14[i] - o13[i]; d2c = fmaf(dc, dc, d2c);
    }
    d2a = wsum(d2a); d2b = wsum(d2b); d2c = wsum(d2c);
    float roc = (sqrtf(d2a) + sqrtf(d2b) + sqrtf(d2c)) * (1.f / 3.f);

    // correlation
    float osum = 0.f;
#pragma unroll
    for (int i = 0; i < 8; i++) osum += o14[i];
    osum = wsum(osum);
    float om = osum * (1.f / 256.f);
    const float* ap = act + ((size_t)b * T_TOT + 13) * ACT_DIM;
    float a0 = ap[j], a1 = ap[32 + j];
    float am = wsum(a0 + a1) * (1.f / 256.f);
    float num = 0.f, do2 = 0.f;
#pragma unroll
    for (int i = 0; i < 8; i++) {
        float oc = o14[i] - om;
        do2 = fmaf(oc, oc, do2);
        float acv = ((i == 0) ? a0 : (i == 1) ? a1 : 0.f) - am;
        num = fmaf(oc, acv, num);
    }
    float da2 = (a0 - am) * (a0 - am) + (a1 - am) * (a1 - am) + 6.f * am * am;
    num = wsum(num); do2 = wsum(do2); da2 = wsum(da2);
    float corr = num / (sqrtf(do2) * sqrtf(da2) + 1e-8f);

    // ---- layernorm + MLP ----
    float* fb = wbuf[warp];
    if (j == 0) { fb[0] = entropy; fb[1] = roc; fb[2] = corr; }
    fb[3 + j] = h;
    __syncwarp();

    float v1 = fb[j];
    float v2 = (j < 3) ? fb[32 + j] : 0.f;
    float mu = wsum(v1 + v2) * (1.f / 35.f);
    float dd1 = v1 - mu;
    float dd2 = (j < 3) ? (v2 - mu) : 0.f;
    float var = wsum(dd1 * dd1 + dd2 * dd2) * (1.f / 35.f);
    float scl = rsqrtf(var + 1e-5f);
    __syncwarp();
    fb[j] = dd1 * scl * gms[j] + bts[j];
    if (j < 3) fb[32 + j] = dd2 * scl * gms[32 + j] + bts[32 + j];
    __syncwarp();

    float* fx1 = fb + 40;
    {
        float acc0 = b1s[j], acc1 = b1s[32 + j];
#pragma unroll
        for (int k = 0; k < 35; k++) {
            float f = fb[k];
            acc0 = fmaf(w1s[j * 35 + k], f, acc0);
            acc1 = fmaf(w1s[(32 + j) * 35 + k], f, acc1);
        }
        fx1[j] = fmaxf(acc0, 0.f);
        fx1[32 + j] = fmaxf(acc1, 0.f);
    }
    __syncwarp();

    float* fx2 = fb + 104;
    {
        float acc = b2s[j];
#pragma unroll
        for (int k = 0; k < 64; k++) acc = fmaf(w2s[j * 65 + k], fx1[k], acc);
        fx2[j] = fmaxf(acc, 0.f);
    }
    __syncwarp();

    float val = -INFINITY;
    if (j < 14) {
        float acc = b3s[j];
#pragma unroll
        for (int k = 0; k < 32; k++) acc = fmaf(w3s[j * 33 + k], fx2[k], acc);
        val = acc;
    }
    int idx = j;
#pragma unroll
    for (int off = 16; off; off >>= 1) {
        float ov = __shfl_down_sync(0xffffffffu, val, off);
        int oi = __shfl_down_sync(0xffffffffu, idx, off);
        if (ov > val || (ov == val && oi < idx)) { val = ov; idx = oi; }
    }
    idx = __shfl_sync(0xffffffffu, idx, 0);

    int wl = idx + 2;
    int s_off = (wl - 1) >> 1;
    int e_off = wl >> 1;

    if (j == 0) out[b] = (float)wl;
    if (j < MAXW) {
        int offp = j - 7;
        float mval = (offp >= -s_off && offp <= e_off) ? 1.f : 0.f;
        out[(size_t)Bn + (size_t)Bn * MAXW * KDIM + (size_t)b * MAXW + j] = mval;
    }
}

// =====================================================================
// Kernel 3: padded window writer. One warp per (b, o) row.
// =====================================================================
__global__ __launch_bounds__(256) void k_win(
    const float* __restrict__ obs, const float* __restrict__ act,
    const float* __restrict__ maskbuf, float* __restrict__ pw, int Bn)
{
    int wg = (blockIdx.x * blockDim.x + threadIdx.x) >> 5;
    int j = threadIdx.x & 31;
    if (wg >= Bn * MAXW) return;
    int b = wg / MAXW;
    int o = wg - b * MAXW;

    float m = maskbuf[(size_t)b * MAXW + o];
    float4* dst = (float4*)(pw + (size_t)(b * MAXW + o) * KDIM);

    if (m != 0.f) {
        const float4* so = (const float4*)(obs + (size_t)(b * T_TOT + 7 + o) * OBS_DIM);
        const float4* sa = (const float4*)(act + (size_t)(b * T_TOT + 7 + o) * ACT_DIM);
        dst[j] = so[j];
        dst[32 + j] = so[32 + j];
        if (j < 16) dst[64 + j] = sa[j];
    } else {
        float4 z = make_float4(0.f, 0.f, 0.f, 0.f);
        dst[j] = z;
        dst[32 + j] = z;
        if (j < 16) dst[64 + j] = z;
    }
}

// =====================================================================
extern "C" void kernel_launch(void* const* d_in, const int* in_sizes, int n_in,
                              void* d_out, int out_size)
{
    const float* obs = (const float*)d_in[0];
    const float* act = (const float*)d_in[1];
    const float* Wih = (const float*)d_in[2];
    const float* Whh = (const float*)d_in[3];
    const float* bih = (const float*)d_in[4];
    const float* bhh = (const float*)d_in[5];
    const float* lng = (const float*)d_in[6];
    const float* lnb = (const float*)d_in[7];
    const float* W1  = (const float*)d_in[8];
    const float* b1  = (const float*)d_in[9];
    const float* W2  = (const float*)d_in[10];
    const float* b2  = (const float*)d_in[11];
    const float* W3  = (const float*)d_in[12];
    const float* b3  = (const float*)d_in[13];

    int Bn = in_sizes[0] / (T_TOT * OBS_DIM);
    if (Bn > MAXB) Bn = MAXB;
    float* out = (float*)d_out;

    int Mtot = Bn * NSTEP;
    int gemm_blocks = (Mtot + BM - 1) / BM;
    k_gemm<<<gemm_blocks, 128>>>(obs, act, Wih, bih, Bn);

    int gru_blocks = (Bn + 7) / 8;
    k_gru<<<gru_blocks, 256>>>(obs, act, Whh, bhh, lng, lnb,
                               W1, b1, W2, b2, W3, b3, out, Bn);

    float* pw = out + Bn;                                  // padded_window region
    const float* maskbuf = out + (size_t)Bn + (size_t)Bn * MAXW * KDIM;
    int win_threads = Bn * MAXW * 32;
    k_win<<<(win_threads + 255) / 256, 256>>>(obs, act, maskbuf, pw, Bn);
}